// round 1
// baseline (speedup 1.0000x reference)
#include <cuda_runtime.h>

#define NMAX 100000
#define EMAX 1600000
#define F_IN 256
#define C1 32
#define C2 16

// ---------------- scratch (device globals: allocation-free) ----------------
__device__ float g_deg[NMAX];
__device__ float g_dinv[NMAX];
__device__ int   g_row[EMAX + NMAX];
__device__ int   g_col[EMAX + NMAX];
__device__ float g_norm[EMAX + NMAX];
__device__ float g_H1[(size_t)NMAX * C1];    // x @ W1
__device__ float g_out1[(size_t)NMAX * C1];  // segment_sum of layer-1 messages
__device__ float g_H2[(size_t)NMAX * C2];    // relu(out1+b1) @ W2
__device__ int   g_is64;

// ---------------- dtype detection (edge_index int64 vs int32) --------------
// If data is little-endian int64 with values < 2^31, every odd 32-bit word is 0.
// Random int32 indices in [0,100000): P(one odd word == 0) ~ 1e-5 -> 32 zeros
// in a row is impossible. Deterministic, runs every launch.
__global__ void k_detect(const int* __restrict__ ei32, int E) {
    int n = E < 64 ? E : 64;
    int is64 = 1;
    for (int i = 0; i < n; i++)
        if (ei32[2 * i + 1] != 0) { is64 = 0; break; }
    g_is64 = is64;
}

// ---------------- init: deg=1 (self loop), out1=0, d_out=b2 ----------------
__global__ void k_init(float* __restrict__ out, const float* __restrict__ b2, int N) {
    int i = blockIdx.x * blockDim.x + threadIdx.x;
    if (i < N * C1) g_out1[i] = 0.f;
    if (i < N)      g_deg[i]  = 1.f;
    if (i < N * C2) out[i]    = b2[i & (C2 - 1)];
}

// ---------------- degree accumulation over col -----------------------------
__global__ void k_deg(const void* __restrict__ ei, const float* __restrict__ w, int E) {
    int e = blockIdx.x * blockDim.x + threadIdx.x;
    if (e >= E) return;
    int c;
    if (g_is64) c = (int)((const long long*)ei)[(size_t)E + e];
    else        c = ((const int*)ei)[E + e];
    atomicAdd(&g_deg[c], w[e]);
}

__global__ void k_dinv(int N) {
    int i = blockIdx.x * blockDim.x + threadIdx.x;
    if (i >= N) return;
    float d = g_deg[i];
    g_dinv[i] = d > 0.f ? rsqrtf(d) : 0.f;
}

// ---------------- normalize edges (incl. self loops as virtual edges) ------
__global__ void k_pre(const void* __restrict__ ei, const float* __restrict__ w,
                      int E, int N) {
    int e = blockIdx.x * blockDim.x + threadIdx.x;
    if (e >= E + N) return;
    int r, c; float wt;
    if (e < E) {
        if (g_is64) {
            const long long* p = (const long long*)ei;
            r = (int)p[e]; c = (int)p[(size_t)E + e];
        } else {
            const int* p = (const int*)ei;
            r = p[e]; c = p[E + e];
        }
        wt = w[e];
    } else {
        r = c = e - E; wt = 1.f;
    }
    g_row[e] = r; g_col[e] = c;
    g_norm[e] = g_dinv[r] * wt * g_dinv[c];
}

// ---------------- GEMM1: H1 = x @ W1   (100000x256 @ 256x32) ---------------
// One thread per row; W1 staged in shared; all lanes read the same sW element
// each step -> conflict-free broadcast LDS.
__global__ void k_gemm1(const float* __restrict__ x, const float* __restrict__ W1, int N) {
    __shared__ float sW[F_IN * C1];  // 32 KB
    for (int i = threadIdx.x; i < F_IN * C1; i += blockDim.x) sW[i] = W1[i];
    __syncthreads();
    int row = blockIdx.x * blockDim.x + threadIdx.x;
    if (row >= N) return;
    float acc[C1];
#pragma unroll
    for (int j = 0; j < C1; j++) acc[j] = 0.f;
    const float4* xr = (const float4*)(x + (size_t)row * F_IN);
#pragma unroll 2
    for (int k4 = 0; k4 < F_IN / 4; k4++) {
        float4 xv = __ldg(&xr[k4]);
        const float* wk = &sW[(k4 * 4) * C1];
#pragma unroll
        for (int j = 0; j < C1; j++) {
            acc[j] += xv.x * wk[j];
            acc[j] += xv.y * wk[C1 + j];
            acc[j] += xv.z * wk[2 * C1 + j];
            acc[j] += xv.w * wk[3 * C1 + j];
        }
    }
    float4* o = (float4*)&g_H1[(size_t)row * C1];
#pragma unroll
    for (int j4 = 0; j4 < C1 / 4; j4++)
        o[j4] = make_float4(acc[4 * j4], acc[4 * j4 + 1], acc[4 * j4 + 2], acc[4 * j4 + 3]);
}

__device__ __forceinline__ void red_add_v4(float* addr, float a, float b, float c, float d) {
    asm volatile("red.global.add.v4.f32 [%0], {%1, %2, %3, %4};"
                 :: "l"(addr), "f"(a), "f"(b), "f"(c), "f"(d) : "memory");
}

// ---------------- scatter layer 1: out1[col] += norm * H1[row] -------------
// 8 lanes per edge; each lane handles one float4 chunk (32 cols).
__global__ void k_scatter1(int T) {
    int idx = blockIdx.x * blockDim.x + threadIdx.x;
    int e = idx >> 3;
    if (e >= T) return;
    int lane = idx & 7;
    int r = g_row[e], c = g_col[e];
    float nrm = g_norm[e];
    float4 h = *(const float4*)&g_H1[(size_t)r * C1 + lane * 4];
    red_add_v4(&g_out1[(size_t)c * C1 + lane * 4],
               nrm * h.x, nrm * h.y, nrm * h.z, nrm * h.w);
}

// ---------------- layer-2 projection: H2 = relu(out1 + b1) @ W2 ------------
__global__ void k_gemm2(const float* __restrict__ b1, const float* __restrict__ W2, int N) {
    __shared__ float sW[C1 * C2];  // 2 KB
    __shared__ float sb[C1];
    for (int i = threadIdx.x; i < C1 * C2; i += blockDim.x) sW[i] = W2[i];
    if (threadIdx.x < C1) sb[threadIdx.x] = b1[threadIdx.x];
    __syncthreads();
    int row = blockIdx.x * blockDim.x + threadIdx.x;
    if (row >= N) return;
    const float4* in = (const float4*)&g_out1[(size_t)row * C1];
    float h[C1];
#pragma unroll
    for (int k4 = 0; k4 < C1 / 4; k4++) {
        float4 v = in[k4];
        h[4 * k4 + 0] = fmaxf(v.x + sb[4 * k4 + 0], 0.f);
        h[4 * k4 + 1] = fmaxf(v.y + sb[4 * k4 + 1], 0.f);
        h[4 * k4 + 2] = fmaxf(v.z + sb[4 * k4 + 2], 0.f);
        h[4 * k4 + 3] = fmaxf(v.w + sb[4 * k4 + 3], 0.f);
    }
    float acc[C2];
#pragma unroll
    for (int j = 0; j < C2; j++) acc[j] = 0.f;
#pragma unroll
    for (int k = 0; k < C1; k++) {
        const float* wk = &sW[k * C2];
#pragma unroll
        for (int j = 0; j < C2; j++) acc[j] += h[k] * wk[j];
    }
    float4* o = (float4*)&g_H2[(size_t)row * C2];
#pragma unroll
    for (int j4 = 0; j4 < C2 / 4; j4++)
        o[j4] = make_float4(acc[4 * j4], acc[4 * j4 + 1], acc[4 * j4 + 2], acc[4 * j4 + 3]);
}

// ---------------- scatter layer 2: out[col] += norm * H2[row] --------------
// 4 lanes per edge (16 cols).
__global__ void k_scatter2(float* __restrict__ out, int T) {
    int idx = blockIdx.x * blockDim.x + threadIdx.x;
    int e = idx >> 2;
    if (e >= T) return;
    int lane = idx & 3;
    int r = g_row[e], c = g_col[e];
    float nrm = g_norm[e];
    float4 h = *(const float4*)&g_H2[(size_t)r * C2 + lane * 4];
    red_add_v4(&out[(size_t)c * C2 + lane * 4],
               nrm * h.x, nrm * h.y, nrm * h.z, nrm * h.w);
}

// ---------------- launch ----------------------------------------------------
extern "C" void kernel_launch(void* const* d_in, const int* in_sizes, int n_in,
                              void* d_out, int out_size) {
    const float* x  = (const float*)d_in[0];
    const void*  ei = d_in[1];
    const float* w  = (const float*)d_in[2];
    const float* W1 = (const float*)d_in[3];
    const float* b1 = (const float*)d_in[4];
    const float* W2 = (const float*)d_in[5];
    const float* b2 = (const float*)d_in[6];
    float* out = (float*)d_out;

    int N = in_sizes[0] / F_IN;
    int E = in_sizes[2];
    int T = E + N;

    k_detect<<<1, 1>>>((const int*)ei, E);
    k_init<<<(N * C1 + 255) / 256, 256>>>(out, b2, N);
    k_deg<<<(E + 255) / 256, 256>>>(ei, w, E);
    k_dinv<<<(N + 255) / 256, 256>>>(N);
    k_pre<<<(T + 255) / 256, 256>>>(ei, w, E, N);
    k_gemm1<<<(N + 255) / 256, 256>>>(x, W1, N);
    k_scatter1<<<(T * 8 + 255) / 256, 256>>>(T);
    k_gemm2<<<(N + 255) / 256, 256>>>(b1, W2, N);
    k_scatter2<<<(T * 4 + 255) / 256, 256>>>(out, T);
}

// round 2
// speedup vs baseline: 1.0035x; 1.0035x over previous
#include <cuda_runtime.h>

#define NMAX 100000
#define EMAX 1600000
#define F_IN 256
#define C1 32
#define C2 16

// ---------------- scratch (device globals: allocation-free) ----------------
__device__ float g_deg[NMAX];
__device__ int2  g_rc[EMAX + NMAX];
__device__ float g_norm[EMAX + NMAX];
__device__ float g_H1[(size_t)NMAX * C1];    // x @ W1
__device__ float g_out1[(size_t)NMAX * C1];  // segment_sum of layer-1 messages
__device__ float g_H2[(size_t)NMAX * C2];    // relu(out1+b1) @ W2
__device__ int   g_is64;

// ---------------- k0: init + parallel dtype detect -------------------------
// int64 edge_index with values < 2^31 => every odd 32-bit word is 0.
// 64 random int32 indices all having zero odd words: P ~ 1e-160. Deterministic.
__global__ void k0_init(float* __restrict__ out, const float* __restrict__ b2,
                        const int* __restrict__ ei32, int N, int E) {
    if (blockIdx.x == 0 && threadIdx.x < 32) {
        int ok = 1;
#pragma unroll
        for (int s = 0; s < 2; s++) {
            int idx = threadIdx.x + 32 * s;
            if (idx < E && idx < 64 && ei32[2 * idx + 1] != 0) ok = 0;
        }
        unsigned m = __ballot_sync(0xffffffffu, ok);
        if (threadIdx.x == 0) g_is64 = (m == 0xffffffffu) ? 1 : 0;
    }
    int i = blockIdx.x * blockDim.x + threadIdx.x;
    if (i < N * C1) g_out1[i] = 0.f;
    if (i < N)      g_deg[i]  = 0.f;
    if (i < N * C2) out[i]    = b2[i & (C2 - 1)];
}

// ---------------- k1: degree atomics ∪ GEMM1 (merged, independent work) ----
// GEMM1: H1 = x @ W1 (100000x256 @ 256x32), one thread per row, packed f32x2
// FMA (halves fma-pipe cycles), W1 staged in shared (broadcast LDS.64, N=1).
__global__ void k1_deg_gemm1(const void* __restrict__ ei, const float* __restrict__ w,
                             const float* __restrict__ x, const float* __restrict__ W1,
                             int N, int E, int degBlocks) {
    __shared__ float sW[F_IN * C1];  // 32 KB
    if ((int)blockIdx.x < degBlocks) {
        int e = blockIdx.x * blockDim.x + threadIdx.x;
        if (e < E) {
            int c;
            if (g_is64) c = (int)((const long long*)ei)[(size_t)E + e];
            else        c = ((const int*)ei)[E + e];
            atomicAdd(&g_deg[c], w[e]);
        }
        return;
    }
    for (int i = threadIdx.x; i < F_IN * C1; i += blockDim.x) sW[i] = W1[i];
    __syncthreads();
    int row = (blockIdx.x - degBlocks) * blockDim.x + threadIdx.x;
    if (row >= N) return;

    unsigned long long acc[C1 / 2];
#pragma unroll
    for (int j = 0; j < C1 / 2; j++) acc[j] = 0ull;  // packed {0.f, 0.f}

    const float4* xr = (const float4*)(x + (size_t)row * F_IN);
#pragma unroll 2
    for (int k4 = 0; k4 < F_IN / 4; k4++) {
        float4 xv = __ldg(&xr[k4]);
        float xs[4] = {xv.x, xv.y, xv.z, xv.w};
#pragma unroll
        for (int s = 0; s < 4; s++) {
            unsigned long long xx;
            asm("mov.b64 %0, {%1, %1};" : "=l"(xx) : "f"(xs[s]));
            const unsigned long long* wp =
                (const unsigned long long*)&sW[(k4 * 4 + s) * C1];
#pragma unroll
            for (int j = 0; j < C1 / 2; j++)
                asm("fma.rn.f32x2 %0, %1, %2, %0;" : "+l"(acc[j]) : "l"(wp[j]), "l"(xx));
        }
    }
    float res[C1];
#pragma unroll
    for (int j = 0; j < C1 / 2; j++)
        asm("mov.b64 {%0, %1}, %2;" : "=f"(res[2 * j]), "=f"(res[2 * j + 1]) : "l"(acc[j]));
    float4* o = (float4*)&g_H1[(size_t)row * C1];
#pragma unroll
    for (int j4 = 0; j4 < C1 / 4; j4++)
        o[j4] = make_float4(res[4 * j4], res[4 * j4 + 1], res[4 * j4 + 2], res[4 * j4 + 3]);
}

// ---------------- k2: normalize edges (self loops as virtual edges) --------
// dinv computed on the fly: deg always >= 1 (self loop) so no zero-guard.
__global__ void k2_pre(const void* __restrict__ ei, const float* __restrict__ w,
                       int E, int N) {
    int e = blockIdx.x * blockDim.x + threadIdx.x;
    if (e >= E + N) return;
    int r, c; float wt;
    if (e < E) {
        if (g_is64) {
            const long long* p = (const long long*)ei;
            r = (int)p[e]; c = (int)p[(size_t)E + e];
        } else {
            const int* p = (const int*)ei;
            r = p[e]; c = p[E + e];
        }
        wt = w[e];
    } else {
        r = c = e - E; wt = 1.f;
    }
    float nr = rsqrtf(g_deg[r] + 1.f);
    float nc = rsqrtf(g_deg[c] + 1.f);
    g_rc[e] = make_int2(r, c);
    g_norm[e] = nr * wt * nc;
}

__device__ __forceinline__ void red_add_v4(float* addr, float a, float b, float c, float d) {
    asm volatile("red.global.add.v4.f32 [%0], {%1, %2, %3, %4};"
                 :: "l"(addr), "f"(a), "f"(b), "f"(c), "f"(d) : "memory");
}

// ---------------- k3: scatter layer 1: out1[col] += norm * H1[row] ---------
// 8 lanes per edge; one LDG.128 gather + one red.v4 per lane.
__global__ void k3_scatter1(int T) {
    int idx = blockIdx.x * blockDim.x + threadIdx.x;
    int e = idx >> 3;
    if (e >= T) return;
    int lane = idx & 7;
    int2 rc = g_rc[e];
    float nrm = g_norm[e];
    float4 h = *(const float4*)&g_H1[(size_t)rc.x * C1 + lane * 4];
    red_add_v4(&g_out1[(size_t)rc.y * C1 + lane * 4],
               nrm * h.x, nrm * h.y, nrm * h.z, nrm * h.w);
}

// ---------------- k4: H2 = relu(out1 + b1) @ W2 ----------------------------
__global__ void k4_gemm2(const float* __restrict__ b1, const float* __restrict__ W2, int N) {
    __shared__ float sW[C1 * C2];
    __shared__ float sb[C1];
    for (int i = threadIdx.x; i < C1 * C2; i += blockDim.x) sW[i] = W2[i];
    if (threadIdx.x < C1) sb[threadIdx.x] = b1[threadIdx.x];
    __syncthreads();
    int row = blockIdx.x * blockDim.x + threadIdx.x;
    if (row >= N) return;
    const float4* in = (const float4*)&g_out1[(size_t)row * C1];
    float h[C1];
#pragma unroll
    for (int k4 = 0; k4 < C1 / 4; k4++) {
        float4 v = in[k4];
        h[4 * k4 + 0] = fmaxf(v.x + sb[4 * k4 + 0], 0.f);
        h[4 * k4 + 1] = fmaxf(v.y + sb[4 * k4 + 1], 0.f);
        h[4 * k4 + 2] = fmaxf(v.z + sb[4 * k4 + 2], 0.f);
        h[4 * k4 + 3] = fmaxf(v.w + sb[4 * k4 + 3], 0.f);
    }
    float acc[C2];
#pragma unroll
    for (int j = 0; j < C2; j++) acc[j] = 0.f;
#pragma unroll
    for (int k = 0; k < C1; k++) {
        const float* wk = &sW[k * C2];
#pragma unroll
        for (int j = 0; j < C2; j++) acc[j] += h[k] * wk[j];
    }
    float4* o = (float4*)&g_H2[(size_t)row * C2];
#pragma unroll
    for (int j4 = 0; j4 < C2 / 4; j4++)
        o[j4] = make_float4(acc[4 * j4], acc[4 * j4 + 1], acc[4 * j4 + 2], acc[4 * j4 + 3]);
}

// ---------------- k5: scatter layer 2: out[col] += norm * H2[row] ----------
__global__ void k5_scatter2(float* __restrict__ out, int T) {
    int idx = blockIdx.x * blockDim.x + threadIdx.x;
    int e = idx >> 2;
    if (e >= T) return;
    int lane = idx & 3;
    int2 rc = g_rc[e];
    float nrm = g_norm[e];
    float4 h = *(const float4*)&g_H2[(size_t)rc.x * C2 + lane * 4];
    red_add_v4(&out[(size_t)rc.y * C2 + lane * 4],
               nrm * h.x, nrm * h.y, nrm * h.z, nrm * h.w);
}

// ---------------- launch ----------------------------------------------------
extern "C" void kernel_launch(void* const* d_in, const int* in_sizes, int n_in,
                              void* d_out, int out_size) {
    const float* x  = (const float*)d_in[0];
    const void*  ei = d_in[1];
    const float* w  = (const float*)d_in[2];
    const float* W1 = (const float*)d_in[3];
    const float* b1 = (const float*)d_in[4];
    const float* W2 = (const float*)d_in[5];
    const float* b2 = (const float*)d_in[6];
    float* out = (float*)d_out;

    int N = in_sizes[0] / F_IN;
    int E = in_sizes[2];
    int T = E + N;

    int degBlocks  = (E + 255) / 256;
    int gemmBlocks = (N + 255) / 256;

    k0_init<<<(N * C1 + 255) / 256, 256>>>(out, b2, (const int*)ei, N, E);
    k1_deg_gemm1<<<degBlocks + gemmBlocks, 256>>>(ei, w, x, W1, N, E, degBlocks);
    k2_pre<<<(T + 255) / 256, 256>>>(ei, w, E, N);
    k3_scatter1<<<(T * 8 + 255) / 256, 256>>>(T);
    k4_gemm2<<<gemmBlocks, 256>>>(b1, W2, N);
    k5_scatter2<<<(T * 4 + 255) / 256, 256>>>(out, T);
}